// round 12
// baseline (speedup 1.0000x reference)
#include <cuda_runtime.h>
#include <cuda_fp16.h>
#include <cstdint>

// LightGCN: out = 0.25*(X + h1 + h2 + h3), h_{k+1} = A h_k
// Pull-based CSR, fp16 gathers/intermediates, fp32 accumulation.
// R12 = R8 (best measured) + 2-way software-pipelined pull loop:
// ncu shows the fp16 pulls are latency-bound (L2=25%, issue=45%), so two
// independent gather streams per lane double the in-flight loads.

#define N_NODES 100000
#define D_FEAT  64
#define MAX_E   1600000
#define SCAN_BS 1024
#define N_SCAN_BLOCKS ((N_NODES + SCAN_BS - 1) / SCAN_BS)   // 98

// Static scratch (no allocation allowed). deg self-restores each call.
__device__ __half g_hX[(size_t)N_NODES * D_FEAT];
__device__ __half g_h1[(size_t)N_NODES * D_FEAT];
__device__ __half g_h2[(size_t)N_NODES * D_FEAT];
__device__ int    g_deg[N_NODES];
__device__ int    g_exloc[N_NODES];
__device__ int    g_blockSums[N_SCAN_BLOCKS];
__device__ int    g_off[N_NODES + 1];
__device__ int    g_rank[MAX_E];
__device__ int2   g_sedge[MAX_E];

// ---- prep: fp32->fp16 convert of X + dst histogram (return value = rank) ----
__global__ void k_prep(const float* __restrict__ X, __half* __restrict__ hX,
                       const int* __restrict__ dst, int n8, int nE) {
    int i = blockIdx.x * blockDim.x + threadIdx.x;
    if (i < n8) {
        const float4* x4 = reinterpret_cast<const float4*>(X);
        float4 a = x4[2 * i];
        float4 b = x4[2 * i + 1];
        __half2 h0 = __floats2half2_rn(a.x, a.y);
        __half2 h1 = __floats2half2_rn(a.z, a.w);
        __half2 h2 = __floats2half2_rn(b.x, b.y);
        __half2 h3 = __floats2half2_rn(b.z, b.w);
        uint4 r;
        r.x = *reinterpret_cast<unsigned*>(&h0);
        r.y = *reinterpret_cast<unsigned*>(&h1);
        r.z = *reinterpret_cast<unsigned*>(&h2);
        r.w = *reinterpret_cast<unsigned*>(&h3);
        reinterpret_cast<uint4*>(hX)[i] = r;
    }
    if (i < nE) g_rank[i] = atomicAdd(&g_deg[dst[i]], 1);
}

// ---- per-block scan: block-local EXCLUSIVE prefix + block sums; resets deg ----
__global__ void k_scan_block(int n) {
    __shared__ int sh[SCAN_BS];
    int t = threadIdx.x;
    int i = blockIdx.x * SCAN_BS + t;
    int v = (i < n) ? g_deg[i] : 0;
    sh[t] = v;
    __syncthreads();
    for (int d = 1; d < SCAN_BS; d <<= 1) {
        int x = (t >= d) ? sh[t - d] : 0;
        __syncthreads();
        sh[t] += x;
        __syncthreads();
    }
    if (i < n) {
        g_exloc[i] = sh[t] - v;   // exclusive within block
        g_deg[i] = 0;             // self-restore for next replay
    }
    if (t == SCAN_BS - 1) g_blockSums[blockIdx.x] = sh[t];
}

// ---- finalize: recompute chunk base from the 98 block sums; write off ----
__global__ void k_finalize(int n, int nE) {
    __shared__ int s_base;
    int chunk = blockIdx.x >> 2;
    if (threadIdx.x < 32) {
        int acc = 0;
        for (int j = (int)threadIdx.x; j < chunk; j += 32) acc += g_blockSums[j];
        #pragma unroll
        for (int o = 16; o; o >>= 1) acc += __shfl_down_sync(0xffffffffu, acc, o);
        if (threadIdx.x == 0) s_base = acc;
    }
    __syncthreads();
    int i = blockIdx.x * 256 + threadIdx.x;
    if (i >= n) return;
    g_off[i] = g_exloc[i] + s_base;
    if (i == n - 1) g_off[n] = nE;
}

// ---- scatter: pure streaming, NO atomics ----
__global__ void k_scatter(const int* __restrict__ src,
                          const int* __restrict__ dst,
                          const float* __restrict__ ew, int nE) {
    int e = blockIdx.x * blockDim.x + threadIdx.x;
    if (e >= nE) return;
    int pos = g_off[dst[e]] + g_rank[e];
    g_sedge[pos] = make_int2(src[e], __float_as_int(ew[e]));
}

// ---------------- Pull SpMM (fp16 gathers, fp32 accumulate) ----------------
// One warp per dst node. Lanes 0-15 = even edges, lanes 16-31 = odd edges.
// Lane c owns features [4c,4c+4): 16 lanes x 8B = the full 128B fp16 row.
// 2-way pipelined: two independent edge streams (e, e+2) with separate
// accumulators -> 2 gather chains in flight per lane (latency-bound loop).

__device__ __forceinline__ float4 warp_node_reduce_h(const __half* __restrict__ Hin,
                                                     int node, int c, int half) {
    int begin = g_off[node], end = g_off[node + 1];
    float4 a0 = make_float4(0.f, 0.f, 0.f, 0.f);
    float4 a1 = make_float4(0.f, 0.f, 0.f, 0.f);
    int e = begin + half;
    for (; e + 2 < end; e += 4) {
        int2 p0 = g_sedge[e];
        int2 p1 = g_sedge[e + 2];
        uint2 u0 = reinterpret_cast<const uint2*>(Hin + (size_t)p0.x * D_FEAT)[c];
        uint2 u1 = reinterpret_cast<const uint2*>(Hin + (size_t)p1.x * D_FEAT)[c];
        float w0 = __int_as_float(p0.y);
        float w1 = __int_as_float(p1.y);
        float2 fa0 = __half22float2(*reinterpret_cast<__half2*>(&u0.x));
        float2 fb0 = __half22float2(*reinterpret_cast<__half2*>(&u0.y));
        float2 fa1 = __half22float2(*reinterpret_cast<__half2*>(&u1.x));
        float2 fb1 = __half22float2(*reinterpret_cast<__half2*>(&u1.y));
        a0.x += w0 * fa0.x; a0.y += w0 * fa0.y; a0.z += w0 * fb0.x; a0.w += w0 * fb0.y;
        a1.x += w1 * fa1.x; a1.y += w1 * fa1.y; a1.z += w1 * fb1.x; a1.w += w1 * fb1.y;
    }
    if (e < end) {
        int2 p0 = g_sedge[e];
        uint2 u0 = reinterpret_cast<const uint2*>(Hin + (size_t)p0.x * D_FEAT)[c];
        float w0 = __int_as_float(p0.y);
        float2 fa0 = __half22float2(*reinterpret_cast<__half2*>(&u0.x));
        float2 fb0 = __half22float2(*reinterpret_cast<__half2*>(&u0.y));
        a0.x += w0 * fa0.x; a0.y += w0 * fa0.y; a0.z += w0 * fb0.x; a0.w += w0 * fb0.y;
    }
    a0.x += a1.x; a0.y += a1.y; a0.z += a1.z; a0.w += a1.w;
    a0.x += __shfl_xor_sync(0xffffffff, a0.x, 16);
    a0.y += __shfl_xor_sync(0xffffffff, a0.y, 16);
    a0.z += __shfl_xor_sync(0xffffffff, a0.z, 16);
    a0.w += __shfl_xor_sync(0xffffffff, a0.w, 16);
    return a0;
}

// Intermediate layer: write fp16 only.
__global__ void k_pull_h(const __half* __restrict__ Hin,
                         __half* __restrict__ Hout) {
    int gwarp = (blockIdx.x * blockDim.x + threadIdx.x) >> 5;
    if (gwarp >= N_NODES) return;
    int lane = threadIdx.x & 31;
    int half = lane >> 4;
    int c    = lane & 15;
    float4 acc = warp_node_reduce_h(Hin, gwarp, c, half);
    if (half == 0) {
        __half2 h0 = __floats2half2_rn(acc.x, acc.y);
        __half2 h1 = __floats2half2_rn(acc.z, acc.w);
        uint2 u;
        u.x = *reinterpret_cast<unsigned*>(&h0);
        u.y = *reinterpret_cast<unsigned*>(&h1);
        reinterpret_cast<uint2*>(Hout + (size_t)gwarp * D_FEAT)[c] = u;
    }
}

// Final layer fused with the mean: out = 0.25*(X + h1 + h2 + h3).
__global__ void k_pull_final_h(const __half* __restrict__ Hin,   // h2 (fp16)
                               const float* __restrict__ X,
                               const __half* __restrict__ H1,
                               float* __restrict__ out) {
    int gwarp = (blockIdx.x * blockDim.x + threadIdx.x) >> 5;
    if (gwarp >= N_NODES) return;
    int lane = threadIdx.x & 31;
    int half = lane >> 4;
    int c    = lane & 15;
    float4 acc = warp_node_reduce_h(Hin, gwarp, c, half);   // h3 chunk
    if (half == 0) {
        size_t idx = (size_t)gwarp * D_FEAT + (c << 2);
        float4 x0 = *reinterpret_cast<const float4*>(X + idx);
        uint2 u1 = reinterpret_cast<const uint2*>(H1  + (size_t)gwarp * D_FEAT)[c];
        uint2 u2 = reinterpret_cast<const uint2*>(Hin + (size_t)gwarp * D_FEAT)[c];
        float2 a1 = __half22float2(*reinterpret_cast<__half2*>(&u1.x));
        float2 b1 = __half22float2(*reinterpret_cast<__half2*>(&u1.y));
        float2 a2 = __half22float2(*reinterpret_cast<__half2*>(&u2.x));
        float2 b2 = __half22float2(*reinterpret_cast<__half2*>(&u2.y));
        float4 o;
        o.x = 0.25f * (x0.x + a1.x + a2.x + acc.x);
        o.y = 0.25f * (x0.y + a1.y + a2.y + acc.y);
        o.z = 0.25f * (x0.z + b1.x + b2.x + acc.z);
        o.w = 0.25f * (x0.w + b1.y + b2.y + acc.w);
        *reinterpret_cast<float4*>(out + idx) = o;
    }
}

extern "C" void kernel_launch(void* const* d_in, const int* in_sizes, int n_in,
                              void* d_out, int out_size) {
    const float* X   = (const float*)d_in[0];
    const int*   src = (const int*)  d_in[1];
    const int*   dst = (const int*)  d_in[2];
    const float* ew  = (const float*)d_in[3];
    float* out = (float*)d_out;
    const int nE = in_sizes[1];

    __half* hX = nullptr;
    __half* h1 = nullptr;
    __half* h2 = nullptr;
    cudaGetSymbolAddress((void**)&hX, g_hX);
    cudaGetSymbolAddress((void**)&h1, g_h1);
    cudaGetSymbolAddress((void**)&h2, g_h2);

    const int TB = 256;
    const int n8       = N_NODES * D_FEAT / 8;
    const int prepN    = (nE > n8) ? nE : n8;
    const int gridPrep = (prepN + TB - 1) / TB;
    const int gridFin  = (N_NODES + 255) / 256;
    const int gridE    = (nE + TB - 1) / TB;
    const int gridPull = (N_NODES * 32 + TB - 1) / TB;   // warp per node

    // --- build dst-sorted CSR ---
    k_prep<<<gridPrep, TB>>>(X, hX, dst, n8, nE);
    k_scan_block<<<N_SCAN_BLOCKS, SCAN_BS>>>(N_NODES);
    k_finalize<<<gridFin, 256>>>(N_NODES, nE);
    k_scatter<<<gridE, TB>>>(src, dst, ew, nE);

    // --- 3 pull layers (pipelined fp16 gathers, fp32 accum + mean) ---
    k_pull_h<<<gridPull, TB>>>(hX, h1);
    k_pull_h<<<gridPull, TB>>>(h1, h2);
    k_pull_final_h<<<gridPull, TB>>>(h2, X, h1, out);
}

// round 13
// speedup vs baseline: 1.2281x; 1.2281x over previous
#include <cuda_runtime.h>
#include <cuda_fp16.h>
#include <cstdint>

// LightGCN: out = 0.25*(X + h1 + h2 + h3), h_{k+1} = A h_k
// Pull-based CSR, fp16 gathers/intermediates, fp32 accumulation.
// R13 = R8 (best measured, 135.7us) with the block scan rewritten as a
// warp-shuffle scan (2 barriers instead of 20). Pull path untouched.

#define N_NODES 100000
#define D_FEAT  64
#define MAX_E   1600000
#define SCAN_BS 1024
#define N_SCAN_BLOCKS ((N_NODES + SCAN_BS - 1) / SCAN_BS)   // 98

// Static scratch (no allocation allowed). deg self-restores each call.
__device__ __half g_hX[(size_t)N_NODES * D_FEAT];
__device__ __half g_h1[(size_t)N_NODES * D_FEAT];
__device__ __half g_h2[(size_t)N_NODES * D_FEAT];
__device__ int    g_deg[N_NODES];
__device__ int    g_exloc[N_NODES];
__device__ int    g_blockSums[N_SCAN_BLOCKS];
__device__ int    g_off[N_NODES + 1];
__device__ int    g_rank[MAX_E];
__device__ int2   g_sedge[MAX_E];

// ---- prep: fp32->fp16 convert of X + dst histogram (return value = rank) ----
__global__ void k_prep(const float* __restrict__ X, __half* __restrict__ hX,
                       const int* __restrict__ dst, int n8, int nE) {
    int i = blockIdx.x * blockDim.x + threadIdx.x;
    if (i < n8) {
        const float4* x4 = reinterpret_cast<const float4*>(X);
        float4 a = x4[2 * i];
        float4 b = x4[2 * i + 1];
        __half2 h0 = __floats2half2_rn(a.x, a.y);
        __half2 h1 = __floats2half2_rn(a.z, a.w);
        __half2 h2 = __floats2half2_rn(b.x, b.y);
        __half2 h3 = __floats2half2_rn(b.z, b.w);
        uint4 r;
        r.x = *reinterpret_cast<unsigned*>(&h0);
        r.y = *reinterpret_cast<unsigned*>(&h1);
        r.z = *reinterpret_cast<unsigned*>(&h2);
        r.w = *reinterpret_cast<unsigned*>(&h3);
        reinterpret_cast<uint4*>(hX)[i] = r;
    }
    if (i < nE) g_rank[i] = atomicAdd(&g_deg[dst[i]], 1);
}

// ---- per-block scan via warp shuffles: block-local EXCLUSIVE prefix +
//      block sums; resets deg. 2 __syncthreads total. ----
__global__ void k_scan_block(int n) {
    __shared__ int warpSums[32];
    int t = threadIdx.x;
    int i = blockIdx.x * SCAN_BS + t;
    int lane = t & 31;
    int wid  = t >> 5;
    int v = (i < n) ? g_deg[i] : 0;

    // warp inclusive scan
    int s = v;
    #pragma unroll
    for (int d = 1; d < 32; d <<= 1) {
        int x = __shfl_up_sync(0xffffffffu, s, d);
        if (lane >= d) s += x;
    }
    if (lane == 31) warpSums[wid] = s;
    __syncthreads();

    // warp 0 scans the 32 warp sums (exclusive)
    if (wid == 0) {
        int ws = warpSums[lane];
        int p = ws;
        #pragma unroll
        for (int d = 1; d < 32; d <<= 1) {
            int x = __shfl_up_sync(0xffffffffu, p, d);
            if (lane >= d) p += x;
        }
        warpSums[lane] = p - ws;   // exclusive base per warp
        if (lane == 31) g_blockSums[blockIdx.x] = p;   // block total
    }
    __syncthreads();

    if (i < n) {
        g_exloc[i] = warpSums[wid] + s - v;   // block-local exclusive
        g_deg[i] = 0;                         // self-restore for next replay
    }
}

// ---- finalize: recompute chunk base from the 98 block sums; write off ----
__global__ void k_finalize(int n, int nE) {
    __shared__ int s_base;
    int chunk = blockIdx.x >> 2;
    if (threadIdx.x < 32) {
        int acc = 0;
        for (int j = (int)threadIdx.x; j < chunk; j += 32) acc += g_blockSums[j];
        #pragma unroll
        for (int o = 16; o; o >>= 1) acc += __shfl_down_sync(0xffffffffu, acc, o);
        if (threadIdx.x == 0) s_base = acc;
    }
    __syncthreads();
    int i = blockIdx.x * 256 + threadIdx.x;
    if (i >= n) return;
    g_off[i] = g_exloc[i] + s_base;
    if (i == n - 1) g_off[n] = nE;
}

// ---- scatter: pure streaming, NO atomics ----
__global__ void k_scatter(const int* __restrict__ src,
                          const int* __restrict__ dst,
                          const float* __restrict__ ew, int nE) {
    int e = blockIdx.x * blockDim.x + threadIdx.x;
    if (e >= nE) return;
    int pos = g_off[dst[e]] + g_rank[e];
    g_sedge[pos] = make_int2(src[e], __float_as_int(ew[e]));
}

// ---------------- Pull SpMM (R8 form, untouched) ----------------
// One warp per dst node. Lanes 0-15 = even edges, lanes 16-31 = odd edges.
// Lane c owns features [4c,4c+4): 16 lanes x 8B = the full 128B fp16 row.

__device__ __forceinline__ float4 warp_node_reduce_h(const __half* __restrict__ Hin,
                                                     int node, int c, int half) {
    int begin = g_off[node], end = g_off[node + 1];
    float4 acc = make_float4(0.f, 0.f, 0.f, 0.f);
    for (int e = begin + half; e < end; e += 2) {
        int2  p = g_sedge[e];
        float w = __int_as_float(p.y);
        uint2 u = reinterpret_cast<const uint2*>(Hin + (size_t)p.x * D_FEAT)[c];
        float2 fa = __half22float2(*reinterpret_cast<__half2*>(&u.x));
        float2 fb = __half22float2(*reinterpret_cast<__half2*>(&u.y));
        acc.x += w * fa.x; acc.y += w * fa.y; acc.z += w * fb.x; acc.w += w * fb.y;
    }
    acc.x += __shfl_xor_sync(0xffffffff, acc.x, 16);
    acc.y += __shfl_xor_sync(0xffffffff, acc.y, 16);
    acc.z += __shfl_xor_sync(0xffffffff, acc.z, 16);
    acc.w += __shfl_xor_sync(0xffffffff, acc.w, 16);
    return acc;
}

// Intermediate layer: write fp16 only.
__global__ void k_pull_h(const __half* __restrict__ Hin,
                         __half* __restrict__ Hout) {
    int gwarp = (blockIdx.x * blockDim.x + threadIdx.x) >> 5;
    if (gwarp >= N_NODES) return;
    int lane = threadIdx.x & 31;
    int half = lane >> 4;
    int c    = lane & 15;
    float4 acc = warp_node_reduce_h(Hin, gwarp, c, half);
    if (half == 0) {
        __half2 h0 = __floats2half2_rn(acc.x, acc.y);
        __half2 h1 = __floats2half2_rn(acc.z, acc.w);
        uint2 u;
        u.x = *reinterpret_cast<unsigned*>(&h0);
        u.y = *reinterpret_cast<unsigned*>(&h1);
        reinterpret_cast<uint2*>(Hout + (size_t)gwarp * D_FEAT)[c] = u;
    }
}

// Final layer fused with the mean: out = 0.25*(X + h1 + h2 + h3).
__global__ void k_pull_final_h(const __half* __restrict__ Hin,   // h2 (fp16)
                               const float* __restrict__ X,
                               const __half* __restrict__ H1,
                               float* __restrict__ out) {
    int gwarp = (blockIdx.x * blockDim.x + threadIdx.x) >> 5;
    if (gwarp >= N_NODES) return;
    int lane = threadIdx.x & 31;
    int half = lane >> 4;
    int c    = lane & 15;
    float4 acc = warp_node_reduce_h(Hin, gwarp, c, half);   // h3 chunk
    if (half == 0) {
        size_t idx = (size_t)gwarp * D_FEAT + (c << 2);
        float4 x0 = *reinterpret_cast<const float4*>(X + idx);
        uint2 u1 = reinterpret_cast<const uint2*>(H1  + (size_t)gwarp * D_FEAT)[c];
        uint2 u2 = reinterpret_cast<const uint2*>(Hin + (size_t)gwarp * D_FEAT)[c];
        float2 a1 = __half22float2(*reinterpret_cast<__half2*>(&u1.x));
        float2 b1 = __half22float2(*reinterpret_cast<__half2*>(&u1.y));
        float2 a2 = __half22float2(*reinterpret_cast<__half2*>(&u2.x));
        float2 b2 = __half22float2(*reinterpret_cast<__half2*>(&u2.y));
        float4 o;
        o.x = 0.25f * (x0.x + a1.x + a2.x + acc.x);
        o.y = 0.25f * (x0.y + a1.y + a2.y + acc.y);
        o.z = 0.25f * (x0.z + b1.x + b2.x + acc.z);
        o.w = 0.25f * (x0.w + b1.y + b2.y + acc.w);
        *reinterpret_cast<float4*>(out + idx) = o;
    }
}

extern "C" void kernel_launch(void* const* d_in, const int* in_sizes, int n_in,
                              void* d_out, int out_size) {
    const float* X   = (const float*)d_in[0];
    const int*   src = (const int*)  d_in[1];
    const int*   dst = (const int*)  d_in[2];
    const float* ew  = (const float*)d_in[3];
    float* out = (float*)d_out;
    const int nE = in_sizes[1];

    __half* hX = nullptr;
    __half* h1 = nullptr;
    __half* h2 = nullptr;
    cudaGetSymbolAddress((void**)&hX, g_hX);
    cudaGetSymbolAddress((void**)&h1, g_h1);
    cudaGetSymbolAddress((void**)&h2, g_h2);

    const int TB = 256;
    const int n8       = N_NODES * D_FEAT / 8;
    const int prepN    = (nE > n8) ? nE : n8;
    const int gridPrep = (prepN + TB - 1) / TB;
    const int gridFin  = (N_NODES + 255) / 256;
    const int gridE    = (nE + TB - 1) / TB;
    const int gridPull = (N_NODES * 32 + TB - 1) / TB;   // warp per node

    // --- build dst-sorted CSR ---
    k_prep<<<gridPrep, TB>>>(X, hX, dst, n8, nE);
    k_scan_block<<<N_SCAN_BLOCKS, SCAN_BS>>>(N_NODES);
    k_finalize<<<gridFin, 256>>>(N_NODES, nE);
    k_scatter<<<gridE, TB>>>(src, dst, ew, nE);

    // --- 3 pull layers (fp16 gathers, fp32 accumulation + mean) ---
    k_pull_h<<<gridPull, TB>>>(hX, h1);
    k_pull_h<<<gridPull, TB>>>(h1, h2);
    k_pull_final_h<<<gridPull, TB>>>(h2, X, h1, out);
}